// round 9
// baseline (speedup 1.0000x reference)
#include <cuda_runtime.h>
#include <cstdint>

#define N_NODES_MAX 100000
#define N_EDGES_MAX 1200000
#define DFEAT 64
#define N_GRAPHS 128

// Scratch (device globals: no allocation allowed anywhere)
__device__ __align__(16) float g_h[N_NODES_MAX * DFEAT];
__device__ int g_src[N_EDGES_MAX];
__device__ int g_dst[N_EDGES_MAX];
__device__ int g_csrc[N_EDGES_MAX];      // CSR: src ids grouped by dst
__device__ int g_gid[N_NODES_MAX];
__device__ int g_deg[N_NODES_MAX];
__device__ int g_start[N_NODES_MAX + 1];
__device__ int g_cur[N_NODES_MAX];
__device__ int g_idx64;                   // 1 if index buffers are int64-laid-out

// ---------------------------------------------------------------------------
// Probe index layout: int64 little-endian => odd int32 words are all zero.
// ---------------------------------------------------------------------------
__global__ void detect_kernel(const int* __restrict__ src, int n) {
    if (threadIdx.x == 0 && blockIdx.x == 0) {
        int allzero = 1;
        int lim = (n > 32) ? 32 : n;
        for (int i = 0; i < lim; i++)
            if (src[2 * i + 1] != 0) allzero = 0;
        g_idx64 = allzero;
    }
}

__device__ __forceinline__ int load_idx(const void* p, int i, int f64) {
    return f64 ? (int)((const long long*)p)[i] : ((const int*)p)[i];
}

// ---------------------------------------------------------------------------
// Prep: normalize indices to int32, zero deg[] and out[]
// ---------------------------------------------------------------------------
__global__ void prep_kernel(const void* __restrict__ src_raw,
                            const void* __restrict__ dst_raw,
                            const void* __restrict__ gid_raw,
                            int* __restrict__ src, int* __restrict__ dst,
                            int* __restrict__ gid, int* __restrict__ deg,
                            float* __restrict__ out,
                            int n_edges, int n_nodes, int out_elems) {
    int i = blockIdx.x * blockDim.x + threadIdx.x;
    int stride = gridDim.x * blockDim.x;
    int f64 = g_idx64;
    for (; i < n_edges; i += stride) {
        src[i] = load_idx(src_raw, i, f64);
        dst[i] = load_idx(dst_raw, i, f64);
        if (i < n_nodes) { gid[i] = load_idx(gid_raw, i, f64); deg[i] = 0; }
        if (i < out_elems) out[i] = 0.f;
    }
}

// ---------------------------------------------------------------------------
// CSR build
// ---------------------------------------------------------------------------
__global__ void degree_kernel(const int* __restrict__ dst, int* __restrict__ deg,
                              int n_edges) {
    int i = blockIdx.x * blockDim.x + threadIdx.x;
    int stride = gridDim.x * blockDim.x;
    for (; i < n_edges; i += stride) atomicAdd(&deg[dst[i]], 1);
}

// Single-block exclusive scan (n <= 100k, 1024 threads)
__global__ void scan_kernel(const int* __restrict__ deg, int* __restrict__ start,
                            int* __restrict__ cur, int n) {
    __shared__ int part[1024];
    int t = threadIdx.x;
    int chunk = (n + 1023) / 1024;
    int lo = t * chunk;
    int hi = lo + chunk; if (hi > n) hi = n;
    int s = 0;
    for (int i = lo; i < hi; i++) s += deg[i];
    part[t] = s;
    __syncthreads();
    // inclusive Hillis-Steele scan
    for (int off = 1; off < 1024; off <<= 1) {
        int v = (t >= off) ? part[t - off] : 0;
        __syncthreads();
        part[t] += v;
        __syncthreads();
    }
    int run = (t > 0) ? part[t - 1] : 0;   // exclusive prefix of this chunk
    for (int i = lo; i < hi; i++) {
        start[i] = run;
        cur[i] = run;
        run += deg[i];
    }
    if (t == 1023) start[n] = run;
}

__global__ void fill_kernel(const int* __restrict__ src, const int* __restrict__ dst,
                            int* __restrict__ cur, int* __restrict__ csrc,
                            int n_edges) {
    int i = blockIdx.x * blockDim.x + threadIdx.x;
    int stride = gridDim.x * blockDim.x;
    for (; i < n_edges; i += stride) {
        int d = dst[i];
        int p = atomicAdd(&cur[d], 1);
        csrc[p] = src[i];
    }
}

// ---------------------------------------------------------------------------
// Fused GIN layer: h_out[v] = act((x[v] + sum_{u in N(v)} x[u]) @ W + b)
// 256 threads/block, 16 nodes/block. Gather phase: 16 threads per node,
// float4 per lane, neighbor rows accumulated in registers (no atomics),
// unrolled x4 for memory-level parallelism.
// GEMM phase: W tile in smem, 4 rows per iteration.
// POOL: run-carry sum-pool into out_pool (graph_id sorted).
// ---------------------------------------------------------------------------
template <bool RELU, bool POOL>
__global__ void __launch_bounds__(256)
gin_layer_kernel(const float* __restrict__ x,
                 const int* __restrict__ start,
                 const int* __restrict__ csrc,
                 const float* __restrict__ W,
                 const float* __restrict__ b,
                 const int* __restrict__ gid,
                 float* __restrict__ out_h,
                 float* __restrict__ out_pool,
                 int n_nodes) {
    __shared__ float Ws[DFEAT * DFEAT];
    __shared__ float bs[DFEAT];
    __shared__ float xs[16 * DFEAT];
    __shared__ float vals[4 * DFEAT];
    __shared__ int sgid[16];

    int tid = threadIdx.x;
    #pragma unroll
    for (int i = 0; i < 16; i++) Ws[tid + i * 256] = W[tid + i * 256];
    if (tid < DFEAT) bs[tid] = b[tid];

    int base = blockIdx.x * 16;
    int grp = tid >> 4;       // node group 0..15
    int lane = tid & 15;      // float4 lane within row
    int v = base + grp;

    if (v < n_nodes) {
        const float4* self = reinterpret_cast<const float4*>(x + (size_t)v * DFEAT);
        float4 acc = __ldg(&self[lane]);
        int s0 = __ldg(&start[v]);
        int s1 = __ldg(&start[v + 1]);
        int e = s0;
        // unrolled x4: keep 4 independent row loads in flight
        for (; e + 4 <= s1; e += 4) {
            int u0 = __ldg(&csrc[e]);
            int u1 = __ldg(&csrc[e + 1]);
            int u2 = __ldg(&csrc[e + 2]);
            int u3 = __ldg(&csrc[e + 3]);
            float4 n0 = __ldg(reinterpret_cast<const float4*>(x + (size_t)u0 * DFEAT) + lane);
            float4 n1 = __ldg(reinterpret_cast<const float4*>(x + (size_t)u1 * DFEAT) + lane);
            float4 n2 = __ldg(reinterpret_cast<const float4*>(x + (size_t)u2 * DFEAT) + lane);
            float4 n3 = __ldg(reinterpret_cast<const float4*>(x + (size_t)u3 * DFEAT) + lane);
            acc.x += n0.x + n1.x + n2.x + n3.x;
            acc.y += n0.y + n1.y + n2.y + n3.y;
            acc.z += n0.z + n1.z + n2.z + n3.z;
            acc.w += n0.w + n1.w + n2.w + n3.w;
        }
        for (; e < s1; e++) {
            int u = __ldg(&csrc[e]);
            float4 nv = __ldg(reinterpret_cast<const float4*>(x + (size_t)u * DFEAT) + lane);
            acc.x += nv.x; acc.y += nv.y; acc.z += nv.z; acc.w += nv.w;
        }
        *reinterpret_cast<float4*>(&xs[grp * DFEAT + lane * 4]) = acc;
    }
    if (POOL && tid < 16) {
        int rr = base + tid;
        sgid[tid] = (rr < n_nodes) ? gid[rr] : -1;
    }
    __syncthreads();

    int r = tid >> 6;         // 0..3
    int col = tid & 63;

    if (!POOL) {
        #pragma unroll
        for (int it = 0; it < 4; it++) {
            int row = base + it * 4 + r;
            if (row < n_nodes) {
                float sum = bs[col];
                const float* xr = &xs[(it * 4 + r) * DFEAT];
                #pragma unroll
                for (int k = 0; k < DFEAT; k++)
                    sum = fmaf(xr[k], Ws[k * DFEAT + col], sum);
                if (RELU) sum = fmaxf(sum, 0.f);
                out_h[(size_t)row * DFEAT + col] = sum;
            }
        }
    } else {
        int g = -1;
        float acc = 0.f;
        #pragma unroll
        for (int it = 0; it < 4; it++) {
            int row = base + it * 4 + r;
            float sum = 0.f;
            if (row < n_nodes) {
                sum = bs[col];
                const float* xr = &xs[(it * 4 + r) * DFEAT];
                #pragma unroll
                for (int k = 0; k < DFEAT; k++)
                    sum = fmaf(xr[k], Ws[k * DFEAT + col], sum);
            }
            vals[tid] = sum;
            __syncthreads();
            if (tid < DFEAT) {
                #pragma unroll
                for (int rr = 0; rr < 4; rr++) {
                    int gr = sgid[it * 4 + rr];
                    if (gr < 0) break;
                    if (gr != g) {
                        if (g >= 0) atomicAdd(&out_pool[g * DFEAT + tid], acc);
                        g = gr;
                        acc = 0.f;
                    }
                    acc += vals[rr * DFEAT + tid];
                }
            }
            __syncthreads();
        }
        if (tid < DFEAT && g >= 0) atomicAdd(&out_pool[g * DFEAT + tid], acc);
    }
}

// ---------------------------------------------------------------------------
// Launch
// ---------------------------------------------------------------------------
extern "C" void kernel_launch(void* const* d_in, const int* in_sizes, int n_in,
                              void* d_out, int out_size) {
    const float* feats = (const float*)d_in[0];
    const void* src_raw = d_in[1];
    const void* dst_raw = d_in[2];
    const void* gid_raw = d_in[3];
    const float* W1 = (const float*)d_in[4];
    const float* b1 = (const float*)d_in[5];
    const float* W2 = (const float*)d_in[6];
    const float* b2 = (const float*)d_in[7];
    float* out = (float*)d_out;

    int n_nodes = in_sizes[0] / DFEAT;
    int n_edges = in_sizes[1];

    float* h; int *src, *dst, *csrc, *gid, *deg, *start, *cur;
    cudaGetSymbolAddress((void**)&h, g_h);
    cudaGetSymbolAddress((void**)&src, g_src);
    cudaGetSymbolAddress((void**)&dst, g_dst);
    cudaGetSymbolAddress((void**)&csrc, g_csrc);
    cudaGetSymbolAddress((void**)&gid, g_gid);
    cudaGetSymbolAddress((void**)&deg, g_deg);
    cudaGetSymbolAddress((void**)&start, g_start);
    cudaGetSymbolAddress((void**)&cur, g_cur);

    int egrid = (n_edges + 255) / 256;

    // 0) probe index layout; normalize indices; zero deg + out
    detect_kernel<<<1, 32>>>((const int*)src_raw, n_edges);
    prep_kernel<<<egrid, 256>>>(src_raw, dst_raw, gid_raw,
                                src, dst, gid, deg, out,
                                n_edges, n_nodes, out_size);

    // 1) CSR build (keyed by dst)
    degree_kernel<<<egrid, 256>>>(dst, deg, n_edges);
    scan_kernel<<<1, 1024>>>(deg, start, cur, n_nodes);
    fill_kernel<<<egrid, 256>>>(src, dst, cur, csrc, n_edges);

    // 2) layer 1: h = relu((feats + gather(feats)) @ W1 + b1)
    int lgrid = (n_nodes + 15) / 16;
    gin_layer_kernel<true, false><<<lgrid, 256>>>(feats, start, csrc, W1, b1,
                                                  gid, h, nullptr, n_nodes);

    // 3) layer 2 + sum-pool: out += (h + gather(h)) @ W2 + b2 per graph
    gin_layer_kernel<false, true><<<lgrid, 256>>>(h, start, csrc, W2, b2,
                                                  gid, nullptr, out, n_nodes);
}

// round 10
// speedup vs baseline: 1.6252x; 1.6252x over previous
#include <cuda_runtime.h>
#include <cstdint>

#define N_NODES_MAX 100000
#define N_EDGES_MAX 1200000
#define DFEAT 64
#define N_GRAPHS 128
#define SCAN_ELEMS 1024                   // elems per scan block (256 thr x 4)
#define MAX_SCAN_BLOCKS 128               // ceil(100000/1024)=98 <= 128

// Scratch (device globals: no allocation allowed anywhere)
__device__ __align__(16) float g_h[N_NODES_MAX * DFEAT];
__device__ int g_src[N_EDGES_MAX];
__device__ int g_dst[N_EDGES_MAX];
__device__ int g_csrc[N_EDGES_MAX];      // CSR: src ids grouped by dst
__device__ int g_gid[N_NODES_MAX];
__device__ int g_deg[N_NODES_MAX];
__device__ int g_start[N_NODES_MAX + 1];
__device__ int g_cur[N_NODES_MAX];
__device__ int g_partial[MAX_SCAN_BLOCKS];
__device__ int g_idx64;                   // 1 if index buffers are int64-laid-out

// ---------------------------------------------------------------------------
// Probe index layout: int64 little-endian => odd int32 words are all zero.
// ---------------------------------------------------------------------------
__global__ void detect_kernel(const int* __restrict__ src, int n) {
    if (threadIdx.x == 0 && blockIdx.x == 0) {
        int allzero = 1;
        int lim = (n > 32) ? 32 : n;
        for (int i = 0; i < lim; i++)
            if (src[2 * i + 1] != 0) allzero = 0;
        g_idx64 = allzero;
    }
}

__device__ __forceinline__ int load_idx(const void* p, int i, int f64) {
    return f64 ? (int)((const long long*)p)[i] : ((const int*)p)[i];
}

// ---------------------------------------------------------------------------
// Prep: normalize indices to int32 AND count degrees (deg pre-zeroed by memset)
// ---------------------------------------------------------------------------
__global__ void prep_kernel(const void* __restrict__ src_raw,
                            const void* __restrict__ dst_raw,
                            const void* __restrict__ gid_raw,
                            int* __restrict__ src, int* __restrict__ dst,
                            int* __restrict__ gid, int* __restrict__ deg,
                            int n_edges, int n_nodes) {
    int i = blockIdx.x * blockDim.x + threadIdx.x;
    int stride = gridDim.x * blockDim.x;
    int f64 = g_idx64;
    for (; i < n_edges; i += stride) {
        int s = load_idx(src_raw, i, f64);
        int d = load_idx(dst_raw, i, f64);
        src[i] = s;
        dst[i] = d;
        atomicAdd(&deg[d], 1);
        if (i < n_nodes) gid[i] = load_idx(gid_raw, i, f64);
    }
}

// ---------------------------------------------------------------------------
// 3-phase parallel exclusive scan of deg -> start/cur
// ---------------------------------------------------------------------------
// Phase A: per-block sums (each block covers SCAN_ELEMS elements)
__global__ void scanA_kernel(const int* __restrict__ deg, int* __restrict__ partial,
                             int n) {
    __shared__ int sdata[256];
    int t = threadIdx.x;
    int base = blockIdx.x * SCAN_ELEMS + t * 4;
    int s = 0;
    #pragma unroll
    for (int i = 0; i < 4; i++) {
        int idx = base + i;
        if (idx < n) s += deg[idx];
    }
    sdata[t] = s;
    __syncthreads();
    #pragma unroll
    for (int off = 128; off > 0; off >>= 1) {
        if (t < off) sdata[t] += sdata[t + off];
        __syncthreads();
    }
    if (t == 0) partial[blockIdx.x] = sdata[0];
}

// Phase B: exclusive scan of block partials (single small block) + start[n]=total
__global__ void scanB_kernel(int* __restrict__ partial, int* __restrict__ start,
                             int nb, int n) {
    __shared__ int tmp[MAX_SCAN_BLOCKS];
    int t = threadIdx.x;
    int v = (t < nb) ? partial[t] : 0;
    tmp[t] = v;
    __syncthreads();
    #pragma unroll
    for (int off = 1; off < MAX_SCAN_BLOCKS; off <<= 1) {
        int u = (t >= off) ? tmp[t - off] : 0;
        __syncthreads();
        tmp[t] += u;
        __syncthreads();
    }
    if (t < nb) partial[t] = (t > 0) ? tmp[t - 1] : 0;   // exclusive
    if (t == MAX_SCAN_BLOCKS - 1) start[n] = tmp[MAX_SCAN_BLOCKS - 1]; // total
}

// Phase C: local exclusive scan + block offset -> start/cur
__global__ void scanC_kernel(const int* __restrict__ deg,
                             const int* __restrict__ partial,
                             int* __restrict__ start, int* __restrict__ cur,
                             int n) {
    __shared__ int sprefix[256];
    int t = threadIdx.x;
    int base = blockIdx.x * SCAN_ELEMS + t * 4;
    int loc[4];
    int s = 0;
    #pragma unroll
    for (int i = 0; i < 4; i++) {
        int idx = base + i;
        loc[i] = (idx < n) ? deg[idx] : 0;
        s += loc[i];
    }
    sprefix[t] = s;
    __syncthreads();
    #pragma unroll
    for (int off = 1; off < 256; off <<= 1) {
        int u = (t >= off) ? sprefix[t - off] : 0;
        __syncthreads();
        sprefix[t] += u;
        __syncthreads();
    }
    int run = partial[blockIdx.x] + ((t > 0) ? sprefix[t - 1] : 0);
    #pragma unroll
    for (int i = 0; i < 4; i++) {
        int idx = base + i;
        if (idx < n) {
            start[idx] = run;
            cur[idx] = run;
            run += loc[i];
        }
    }
}

__global__ void fill_kernel(const int* __restrict__ src, const int* __restrict__ dst,
                            int* __restrict__ cur, int* __restrict__ csrc,
                            int n_edges) {
    int i = blockIdx.x * blockDim.x + threadIdx.x;
    int stride = gridDim.x * blockDim.x;
    for (; i < n_edges; i += stride) {
        int d = dst[i];
        int p = atomicAdd(&cur[d], 1);
        csrc[p] = src[i];
    }
}

// ---------------------------------------------------------------------------
// Fused GIN layer: h_out[v] = act((x[v] + sum_{u in N(v)} x[u]) @ W + b)
// 256 threads/block, 16 nodes/block. Gather phase: 16 threads per node,
// float4 per lane, register accumulation, x4 unroll for MLP.
// POOL: run-carry sum-pool into out_pool (graph_id sorted).
// ---------------------------------------------------------------------------
template <bool RELU, bool POOL>
__global__ void __launch_bounds__(256)
gin_layer_kernel(const float* __restrict__ x,
                 const int* __restrict__ start,
                 const int* __restrict__ csrc,
                 const float* __restrict__ W,
                 const float* __restrict__ b,
                 const int* __restrict__ gid,
                 float* __restrict__ out_h,
                 float* __restrict__ out_pool,
                 int n_nodes) {
    __shared__ float Ws[DFEAT * DFEAT];
    __shared__ float bs[DFEAT];
    __shared__ float xs[16 * DFEAT];
    __shared__ float vals[4 * DFEAT];
    __shared__ int sgid[16];

    int tid = threadIdx.x;
    #pragma unroll
    for (int i = 0; i < 16; i++) Ws[tid + i * 256] = W[tid + i * 256];
    if (tid < DFEAT) bs[tid] = b[tid];

    int base = blockIdx.x * 16;
    int grp = tid >> 4;       // node group 0..15
    int lane = tid & 15;      // float4 lane within row
    int v = base + grp;

    if (v < n_nodes) {
        const float4* self = reinterpret_cast<const float4*>(x + (size_t)v * DFEAT);
        float4 acc = __ldg(&self[lane]);
        int s0 = __ldg(&start[v]);
        int s1 = __ldg(&start[v + 1]);
        int e = s0;
        for (; e + 4 <= s1; e += 4) {
            int u0 = __ldg(&csrc[e]);
            int u1 = __ldg(&csrc[e + 1]);
            int u2 = __ldg(&csrc[e + 2]);
            int u3 = __ldg(&csrc[e + 3]);
            float4 n0 = __ldg(reinterpret_cast<const float4*>(x + (size_t)u0 * DFEAT) + lane);
            float4 n1 = __ldg(reinterpret_cast<const float4*>(x + (size_t)u1 * DFEAT) + lane);
            float4 n2 = __ldg(reinterpret_cast<const float4*>(x + (size_t)u2 * DFEAT) + lane);
            float4 n3 = __ldg(reinterpret_cast<const float4*>(x + (size_t)u3 * DFEAT) + lane);
            acc.x += n0.x + n1.x + n2.x + n3.x;
            acc.y += n0.y + n1.y + n2.y + n3.y;
            acc.z += n0.z + n1.z + n2.z + n3.z;
            acc.w += n0.w + n1.w + n2.w + n3.w;
        }
        for (; e < s1; e++) {
            int u = __ldg(&csrc[e]);
            float4 nv = __ldg(reinterpret_cast<const float4*>(x + (size_t)u * DFEAT) + lane);
            acc.x += nv.x; acc.y += nv.y; acc.z += nv.z; acc.w += nv.w;
        }
        *reinterpret_cast<float4*>(&xs[grp * DFEAT + lane * 4]) = acc;
    }
    if (POOL && tid < 16) {
        int rr = base + tid;
        sgid[tid] = (rr < n_nodes) ? gid[rr] : -1;
    }
    __syncthreads();

    int r = tid >> 6;         // 0..3
    int col = tid & 63;

    if (!POOL) {
        #pragma unroll
        for (int it = 0; it < 4; it++) {
            int row = base + it * 4 + r;
            if (row < n_nodes) {
                float sum = bs[col];
                const float* xr = &xs[(it * 4 + r) * DFEAT];
                #pragma unroll
                for (int k = 0; k < DFEAT; k++)
                    sum = fmaf(xr[k], Ws[k * DFEAT + col], sum);
                if (RELU) sum = fmaxf(sum, 0.f);
                out_h[(size_t)row * DFEAT + col] = sum;
            }
        }
    } else {
        int g = -1;
        float acc = 0.f;
        #pragma unroll
        for (int it = 0; it < 4; it++) {
            int row = base + it * 4 + r;
            float sum = 0.f;
            if (row < n_nodes) {
                sum = bs[col];
                const float* xr = &xs[(it * 4 + r) * DFEAT];
                #pragma unroll
                for (int k = 0; k < DFEAT; k++)
                    sum = fmaf(xr[k], Ws[k * DFEAT + col], sum);
            }
            vals[tid] = sum;
            __syncthreads();
            if (tid < DFEAT) {
                #pragma unroll
                for (int rr = 0; rr < 4; rr++) {
                    int gr = sgid[it * 4 + rr];
                    if (gr < 0) break;
                    if (gr != g) {
                        if (g >= 0) atomicAdd(&out_pool[g * DFEAT + tid], acc);
                        g = gr;
                        acc = 0.f;
                    }
                    acc += vals[rr * DFEAT + tid];
                }
            }
            __syncthreads();
        }
        if (tid < DFEAT && g >= 0) atomicAdd(&out_pool[g * DFEAT + tid], acc);
    }
}

// ---------------------------------------------------------------------------
// Launch
// ---------------------------------------------------------------------------
extern "C" void kernel_launch(void* const* d_in, const int* in_sizes, int n_in,
                              void* d_out, int out_size) {
    const float* feats = (const float*)d_in[0];
    const void* src_raw = d_in[1];
    const void* dst_raw = d_in[2];
    const void* gid_raw = d_in[3];
    const float* W1 = (const float*)d_in[4];
    const float* b1 = (const float*)d_in[5];
    const float* W2 = (const float*)d_in[6];
    const float* b2 = (const float*)d_in[7];
    float* out = (float*)d_out;

    int n_nodes = in_sizes[0] / DFEAT;
    int n_edges = in_sizes[1];

    float* h; int *src, *dst, *csrc, *gid, *deg, *start, *cur, *partial;
    cudaGetSymbolAddress((void**)&h, g_h);
    cudaGetSymbolAddress((void**)&src, g_src);
    cudaGetSymbolAddress((void**)&dst, g_dst);
    cudaGetSymbolAddress((void**)&csrc, g_csrc);
    cudaGetSymbolAddress((void**)&gid, g_gid);
    cudaGetSymbolAddress((void**)&deg, g_deg);
    cudaGetSymbolAddress((void**)&start, g_start);
    cudaGetSymbolAddress((void**)&cur, g_cur);
    cudaGetSymbolAddress((void**)&partial, g_partial);

    int egrid = (n_edges + 255) / 256;
    int sblocks = (n_nodes + SCAN_ELEMS - 1) / SCAN_ELEMS;

    // 0) zero deg + out (async memsets are graph-capturable, no allocation)
    cudaMemsetAsync(deg, 0, n_nodes * sizeof(int));
    cudaMemsetAsync(out, 0, (size_t)out_size * sizeof(float));

    // 1) probe layout; convert indices + count degrees in one pass
    detect_kernel<<<1, 32>>>((const int*)src_raw, n_edges);
    prep_kernel<<<egrid, 256>>>(src_raw, dst_raw, gid_raw,
                                src, dst, gid, deg, n_edges, n_nodes);

    // 2) parallel exclusive scan deg -> start/cur
    scanA_kernel<<<sblocks, 256>>>(deg, partial, n_nodes);
    scanB_kernel<<<1, MAX_SCAN_BLOCKS>>>(partial, start, sblocks, n_nodes);
    scanC_kernel<<<sblocks, 256>>>(deg, partial, start, cur, n_nodes);

    // 3) CSR fill
    fill_kernel<<<egrid, 256>>>(src, dst, cur, csrc, n_edges);

    // 4) layer 1: h = relu((feats + gather(feats)) @ W1 + b1)
    int lgrid = (n_nodes + 15) / 16;
    gin_layer_kernel<true, false><<<lgrid, 256>>>(feats, start, csrc, W1, b1,
                                                  gid, h, nullptr, n_nodes);

    // 5) layer 2 + sum-pool: out += (h + gather(h)) @ W2 + b2 per graph
    gin_layer_kernel<false, true><<<lgrid, 256>>>(h, start, csrc, W2, b2,
                                                  gid, nullptr, out, n_nodes);
}

// round 12
// speedup vs baseline: 1.8639x; 1.1469x over previous
#include <cuda_runtime.h>
#include <cstdint>

#define N_NODES_MAX 100000
#define N_EDGES_MAX 1200000
#define DFEAT 64
#define N_GRAPHS 128
#define SCAN_ELEMS 1024                   // elems per scan block (256 thr x 4)
#define MAX_SCAN_BLOCKS 128               // ceil(100000/1024)=98 <= 128
#define XS_STRIDE 68                      // 64 + 4 pad: rows land on different banks

// Scratch (device globals: no allocation allowed anywhere)
__device__ __align__(16) float g_h[N_NODES_MAX * DFEAT];
__device__ int g_dst[N_EDGES_MAX];
__device__ int g_csrc[N_EDGES_MAX];      // CSR: src ids grouped by dst
__device__ int g_gid[N_NODES_MAX];
__device__ int g_deg[N_NODES_MAX];
__device__ int g_start[N_NODES_MAX + 1];
__device__ int g_cur[N_NODES_MAX];
__device__ int g_partial[MAX_SCAN_BLOCKS];
__device__ int g_idx64;                   // 1 if index buffers are int64-laid-out

// ---------------------------------------------------------------------------
// Probe index layout: int64 little-endian => odd int32 words are all zero.
// ---------------------------------------------------------------------------
__global__ void detect_kernel(const int* __restrict__ src, int n) {
    if (threadIdx.x == 0 && blockIdx.x == 0) {
        int allzero = 1;
        int lim = (n > 32) ? 32 : n;
        for (int i = 0; i < lim; i++)
            if (src[2 * i + 1] != 0) allzero = 0;
        g_idx64 = allzero;
    }
}

__device__ __forceinline__ int load_idx(const void* p, int i, int f64) {
    return f64 ? (int)((const long long*)p)[i] : ((const int*)p)[i];
}

// ---------------------------------------------------------------------------
// Prep: stage dst as int32, count degrees (deg pre-zeroed), stage gid
// ---------------------------------------------------------------------------
__global__ void prep_kernel(const void* __restrict__ dst_raw,
                            const void* __restrict__ gid_raw,
                            int* __restrict__ dst,
                            int* __restrict__ gid, int* __restrict__ deg,
                            int n_edges, int n_nodes) {
    int i = blockIdx.x * blockDim.x + threadIdx.x;
    int stride = gridDim.x * blockDim.x;
    int f64 = g_idx64;
    for (; i < n_edges; i += stride) {
        int d = load_idx(dst_raw, i, f64);
        dst[i] = d;
        atomicAdd(&deg[d], 1);
        if (i < n_nodes) gid[i] = load_idx(gid_raw, i, f64);
    }
}

// ---------------------------------------------------------------------------
// 3-phase parallel exclusive scan of deg -> start/cur
// ---------------------------------------------------------------------------
__global__ void scanA_kernel(const int* __restrict__ deg, int* __restrict__ partial,
                             int n) {
    __shared__ int sdata[256];
    int t = threadIdx.x;
    int base = blockIdx.x * SCAN_ELEMS + t * 4;
    int s = 0;
    #pragma unroll
    for (int i = 0; i < 4; i++) {
        int idx = base + i;
        if (idx < n) s += deg[idx];
    }
    sdata[t] = s;
    __syncthreads();
    #pragma unroll
    for (int off = 128; off > 0; off >>= 1) {
        if (t < off) sdata[t] += sdata[t + off];
        __syncthreads();
    }
    if (t == 0) partial[blockIdx.x] = sdata[0];
}

__global__ void scanB_kernel(int* __restrict__ partial, int* __restrict__ start,
                             int nb, int n) {
    __shared__ int tmp[MAX_SCAN_BLOCKS];
    int t = threadIdx.x;
    int v = (t < nb) ? partial[t] : 0;
    tmp[t] = v;
    __syncthreads();
    #pragma unroll
    for (int off = 1; off < MAX_SCAN_BLOCKS; off <<= 1) {
        int u = (t >= off) ? tmp[t - off] : 0;
        __syncthreads();
        tmp[t] += u;
        __syncthreads();
    }
    if (t < nb) partial[t] = (t > 0) ? tmp[t - 1] : 0;   // exclusive
    if (t == MAX_SCAN_BLOCKS - 1) start[n] = tmp[MAX_SCAN_BLOCKS - 1]; // total
}

__global__ void scanC_kernel(const int* __restrict__ deg,
                             const int* __restrict__ partial,
                             int* __restrict__ start, int* __restrict__ cur,
                             int n) {
    __shared__ int sprefix[256];
    int t = threadIdx.x;
    int base = blockIdx.x * SCAN_ELEMS + t * 4;
    int loc[4];
    int s = 0;
    #pragma unroll
    for (int i = 0; i < 4; i++) {
        int idx = base + i;
        loc[i] = (idx < n) ? deg[idx] : 0;
        s += loc[i];
    }
    sprefix[t] = s;
    __syncthreads();
    #pragma unroll
    for (int off = 1; off < 256; off <<= 1) {
        int u = (t >= off) ? sprefix[t - off] : 0;
        __syncthreads();
        sprefix[t] += u;
        __syncthreads();
    }
    int run = partial[blockIdx.x] + ((t > 0) ? sprefix[t - 1] : 0);
    #pragma unroll
    for (int i = 0; i < 4; i++) {
        int idx = base + i;
        if (idx < n) {
            start[idx] = run;
            cur[idx] = run;
            run += loc[i];
        }
    }
}

// fill: src converted inline from raw (never staged)
__global__ void fill_kernel(const void* __restrict__ src_raw,
                            const int* __restrict__ dst,
                            int* __restrict__ cur, int* __restrict__ csrc,
                            int n_edges) {
    int i = blockIdx.x * blockDim.x + threadIdx.x;
    int stride = gridDim.x * blockDim.x;
    int f64 = g_idx64;
    for (; i < n_edges; i += stride) {
        int d = dst[i];
        int p = atomicAdd(&cur[d], 1);
        csrc[p] = load_idx(src_raw, i, f64);
    }
}

// ---------------------------------------------------------------------------
// Fused GIN layer: h_out[v] = act((x[v] + sum_{u in N(v)} x[u]) @ W + b)
// 256 threads/block, 16 nodes/block.
// Gather: 16 threads/node, float4/lane, register accumulation, x4 unroll.
// GEMM: thread = (row, 4 cols); Ws via LDS.128 (dedup 2wf/warp/k), xs float4
//       in regs; xs padded stride 68 to avoid 2-row bank conflicts.
// POOL: run-carry sum-pool into out_pool (graph_id sorted).
// ---------------------------------------------------------------------------
template <bool RELU, bool POOL>
__global__ void __launch_bounds__(256)
gin_layer_kernel(const float* __restrict__ x,
                 const int* __restrict__ start,
                 const int* __restrict__ csrc,
                 const float* __restrict__ W,
                 const float* __restrict__ b,
                 const int* __restrict__ gid,
                 float* __restrict__ out_h,
                 float* __restrict__ out_pool,
                 int n_nodes) {
    __shared__ float Ws[DFEAT * DFEAT];
    __shared__ float bs[DFEAT];
    __shared__ float xs[16 * XS_STRIDE];
    __shared__ float vals[16 * XS_STRIDE];
    __shared__ int sgid[16];

    int tid = threadIdx.x;
    #pragma unroll
    for (int i = 0; i < 16; i++) Ws[tid + i * 256] = W[tid + i * 256];
    if (tid < DFEAT) bs[tid] = b[tid];

    int base = blockIdx.x * 16;
    int grp = tid >> 4;       // node / row 0..15
    int lane = tid & 15;      // float4 lane / col group
    int v = base + grp;

    if (v < n_nodes) {
        const float4* self = reinterpret_cast<const float4*>(x + (size_t)v * DFEAT);
        float4 acc = __ldg(&self[lane]);
        int s0 = __ldg(&start[v]);
        int s1 = __ldg(&start[v + 1]);
        int e = s0;
        for (; e + 4 <= s1; e += 4) {
            int u0 = __ldg(&csrc[e]);
            int u1 = __ldg(&csrc[e + 1]);
            int u2 = __ldg(&csrc[e + 2]);
            int u3 = __ldg(&csrc[e + 3]);
            float4 n0 = __ldg(reinterpret_cast<const float4*>(x + (size_t)u0 * DFEAT) + lane);
            float4 n1 = __ldg(reinterpret_cast<const float4*>(x + (size_t)u1 * DFEAT) + lane);
            float4 n2 = __ldg(reinterpret_cast<const float4*>(x + (size_t)u2 * DFEAT) + lane);
            float4 n3 = __ldg(reinterpret_cast<const float4*>(x + (size_t)u3 * DFEAT) + lane);
            acc.x += n0.x + n1.x + n2.x + n3.x;
            acc.y += n0.y + n1.y + n2.y + n3.y;
            acc.z += n0.z + n1.z + n2.z + n3.z;
            acc.w += n0.w + n1.w + n2.w + n3.w;
        }
        for (; e < s1; e++) {
            int u = __ldg(&csrc[e]);
            float4 nv = __ldg(reinterpret_cast<const float4*>(x + (size_t)u * DFEAT) + lane);
            acc.x += nv.x; acc.y += nv.y; acc.z += nv.z; acc.w += nv.w;
        }
        *reinterpret_cast<float4*>(&xs[grp * XS_STRIDE + lane * 4]) = acc;
    }
    if (POOL && tid < 16) {
        int rr = base + tid;
        sgid[tid] = (rr < n_nodes) ? gid[rr] : -1;
    }
    __syncthreads();

    // GEMM: thread handles (row = grp, cols = lane*4 .. lane*4+3)
    int row = base + grp;
    float4 acc4 = reinterpret_cast<const float4*>(bs)[lane];
    #pragma unroll
    for (int k4 = 0; k4 < 16; k4++) {
        float4 xv = *reinterpret_cast<const float4*>(&xs[grp * XS_STRIDE + k4 * 4]);
        const float* wp = &Ws[(k4 * 4) * DFEAT + lane * 4];
        float4 w0 = *reinterpret_cast<const float4*>(wp);
        float4 w1 = *reinterpret_cast<const float4*>(wp + DFEAT);
        float4 w2 = *reinterpret_cast<const float4*>(wp + 2 * DFEAT);
        float4 w3 = *reinterpret_cast<const float4*>(wp + 3 * DFEAT);
        acc4.x = fmaf(xv.x, w0.x, acc4.x);
        acc4.y = fmaf(xv.x, w0.y, acc4.y);
        acc4.z = fmaf(xv.x, w0.z, acc4.z);
        acc4.w = fmaf(xv.x, w0.w, acc4.w);
        acc4.x = fmaf(xv.y, w1.x, acc4.x);
        acc4.y = fmaf(xv.y, w1.y, acc4.y);
        acc4.z = fmaf(xv.y, w1.z, acc4.z);
        acc4.w = fmaf(xv.y, w1.w, acc4.w);
        acc4.x = fmaf(xv.z, w2.x, acc4.x);
        acc4.y = fmaf(xv.z, w2.y, acc4.y);
        acc4.z = fmaf(xv.z, w2.z, acc4.z);
        acc4.w = fmaf(xv.z, w2.w, acc4.w);
        acc4.x = fmaf(xv.w, w3.x, acc4.x);
        acc4.y = fmaf(xv.w, w3.y, acc4.y);
        acc4.z = fmaf(xv.w, w3.z, acc4.z);
        acc4.w = fmaf(xv.w, w3.w, acc4.w);
    }

    if (!POOL) {
        if (row < n_nodes) {
            if (RELU) {
                acc4.x = fmaxf(acc4.x, 0.f);
                acc4.y = fmaxf(acc4.y, 0.f);
                acc4.z = fmaxf(acc4.z, 0.f);
                acc4.w = fmaxf(acc4.w, 0.f);
            }
            *reinterpret_cast<float4*>(&out_h[(size_t)row * DFEAT + lane * 4]) = acc4;
        }
    } else {
        *reinterpret_cast<float4*>(&vals[grp * XS_STRIDE + lane * 4]) = acc4;
        __syncthreads();
        // 64 threads reduce 16 rows with run-carry over sorted graph ids
        if (tid < DFEAT) {
            int g = -1;
            float acc = 0.f;
            #pragma unroll
            for (int rr = 0; rr < 16; rr++) {
                int gr = sgid[rr];
                if (gr < 0) break;
                if (gr != g) {
                    if (g >= 0) atomicAdd(&out_pool[g * DFEAT + tid], acc);
                    g = gr;
                    acc = 0.f;
                }
                acc += vals[rr * XS_STRIDE + tid];
            }
            if (g >= 0) atomicAdd(&out_pool[g * DFEAT + tid], acc);
        }
    }
}

// ---------------------------------------------------------------------------
// Launch
// ---------------------------------------------------------------------------
extern "C" void kernel_launch(void* const* d_in, const int* in_sizes, int n_in,
                              void* d_out, int out_size) {
    const float* feats = (const float*)d_in[0];
    const void* src_raw = d_in[1];
    const void* dst_raw = d_in[2];
    const void* gid_raw = d_in[3];
    const float* W1 = (const float*)d_in[4];
    const float* b1 = (const float*)d_in[5];
    const float* W2 = (const float*)d_in[6];
    const float* b2 = (const float*)d_in[7];
    float* out = (float*)d_out;

    int n_nodes = in_sizes[0] / DFEAT;
    int n_edges = in_sizes[1];

    float* h; int *dst, *csrc, *gid, *deg, *start, *cur, *partial;
    cudaGetSymbolAddress((void**)&h, g_h);
    cudaGetSymbolAddress((void**)&dst, g_dst);
    cudaGetSymbolAddress((void**)&csrc, g_csrc);
    cudaGetSymbolAddress((void**)&gid, g_gid);
    cudaGetSymbolAddress((void**)&deg, g_deg);
    cudaGetSymbolAddress((void**)&start, g_start);
    cudaGetSymbolAddress((void**)&cur, g_cur);
    cudaGetSymbolAddress((void**)&partial, g_partial);

    int egrid = (n_edges + 255) / 256;
    int sblocks = (n_nodes + SCAN_ELEMS - 1) / SCAN_ELEMS;

    // 0) zero deg + out (graph-capturable async memsets; no allocation)
    cudaMemsetAsync(deg, 0, n_nodes * sizeof(int));
    cudaMemsetAsync(out, 0, (size_t)out_size * sizeof(float));

    // 1) probe layout; stage dst/gid + count degrees
    detect_kernel<<<1, 32>>>((const int*)src_raw, n_edges);
    prep_kernel<<<egrid, 256>>>(dst_raw, gid_raw, dst, gid, deg,
                                n_edges, n_nodes);

    // 2) parallel exclusive scan deg -> start/cur
    scanA_kernel<<<sblocks, 256>>>(deg, partial, n_nodes);
    scanB_kernel<<<1, MAX_SCAN_BLOCKS>>>(partial, start, sblocks, n_nodes);
    scanC_kernel<<<sblocks, 256>>>(deg, partial, start, cur, n_nodes);

    // 3) CSR fill (src converted inline)
    fill_kernel<<<egrid, 256>>>(src_raw, dst, cur, csrc, n_edges);

    // 4) layer 1: h = relu((feats + gather(feats)) @ W1 + b1)
    int lgrid = (n_nodes + 15) / 16;
    gin_layer_kernel<true, false><<<lgrid, 256>>>(feats, start, csrc, W1, b1,
                                                  gid, h, nullptr, n_nodes);

    // 5) layer 2 + sum-pool: out += (h + gather(h)) @ W2 + b2 per graph
    gin_layer_kernel<false, true><<<lgrid, 256>>>(h, start, csrc, W2, b2,
                                                  gid, nullptr, out, n_nodes);
}